// round 7
// baseline (speedup 1.0000x reference)
#include <cuda_runtime.h>
#include <cuda_bf16.h>
#include <math.h>

#define N_NODES 4096
#define N_EDGES 8192
#define D       64
#define D3      67      // D + 3
#define F1      134     // 2*(D+3)
#define F2      201     // 3*(D+3)

// ---------------- device scratch (no allocation allowed) --------------------
__device__ int   g_seg_i[N_EDGES];
__device__ int   g_seg_o[N_EDGES];
__device__ __align__(16) float g_H0[N_NODES * D3];
__device__ __align__(16) float g_H1[N_NODES * D3];
__device__ __align__(16) float g_MI[N_NODES * D3];   // zeroed at load; re-zeroed by node kernel
__device__ __align__(16) float g_MO[N_NODES * D3];

// ---------------- packed f32x2 helpers ---------------------------------------
typedef unsigned long long ull;
__device__ __forceinline__ ull pack2(float a, float b) {
    ull r; asm("mov.b64 %0,{%1,%2};" : "=l"(r) : "f"(a), "f"(b)); return r;
}
__device__ __forceinline__ void unpack2(ull v, float& a, float& b) {
    asm("mov.b64 {%0,%1},%2;" : "=f"(a), "=f"(b) : "l"(v));
}
__device__ __forceinline__ ull fma2(ull a, ull b, ull c) {
    ull d; asm("fma.rn.f32x2 %0,%1,%2,%3;" : "=l"(d) : "l"(a), "l"(b), "l"(c)); return d;
}
__device__ __forceinline__ float sigmoidf_(float x) { return 1.f / (1.f + __expf(-x)); }

// ---------------- 1. extract (flat, one-shot, 64 B/thread) -------------------
__global__ void __launch_bounds__(256)
extract_kernel(const float* __restrict__ Ri, const float* __restrict__ Ro) {
    const unsigned total4 = (unsigned)N_NODES * N_EDGES / 4;   // 8,388,608 float4 per matrix
    unsigned tid = blockIdx.x * 256u + threadIdx.x;            // 0 .. 4,194,303
    const float4* src; int* dst; unsigned b;
    if (tid < total4 / 4) { src = (const float4*)Ri; dst = g_seg_i; b = tid * 4u; }
    else                  { src = (const float4*)Ro; dst = g_seg_o; b = (tid - total4 / 4) * 4u; }
    float4 v0 = __ldcs(&src[b + 0]);
    float4 v1 = __ldcs(&src[b + 1]);
    float4 v2 = __ldcs(&src[b + 2]);
    float4 v3 = __ldcs(&src[b + 3]);
    unsigned g = b * 4u;              // 16 | 8192 so the run never crosses a row
    int n = g >> 13;
    int e = g & (N_EDGES - 1);
    if (v0.x != 0.f) dst[e + 0]  = n;
    if (v0.y != 0.f) dst[e + 1]  = n;
    if (v0.z != 0.f) dst[e + 2]  = n;
    if (v0.w != 0.f) dst[e + 3]  = n;
    if (v1.x != 0.f) dst[e + 4]  = n;
    if (v1.y != 0.f) dst[e + 5]  = n;
    if (v1.z != 0.f) dst[e + 6]  = n;
    if (v1.w != 0.f) dst[e + 7]  = n;
    if (v2.x != 0.f) dst[e + 8]  = n;
    if (v2.y != 0.f) dst[e + 9]  = n;
    if (v2.z != 0.f) dst[e + 10] = n;
    if (v2.w != 0.f) dst[e + 11] = n;
    if (v3.x != 0.f) dst[e + 12] = n;
    if (v3.y != 0.f) dst[e + 13] = n;
    if (v3.z != 0.f) dst[e + 14] = n;
    if (v3.w != 0.f) dst[e + 15] = n;
}

// ---------------- 2. input net -----------------------------------------------
__global__ void __launch_bounds__(256)
input_kernel(const float* __restrict__ X, const float* __restrict__ W_in,
             const float* __restrict__ b_in, float* __restrict__ H) {
    int t = blockIdx.x * 256 + threadIdx.x;
    int n = t >> 6, d = t & 63;
    float x0 = X[n * 3 + 0], x1 = X[n * 3 + 1], x2 = X[n * 3 + 2];
    float h = tanhf(x0 * W_in[d] + x1 * W_in[64 + d] + x2 * W_in[128 + d] + b_in[d]);
    H[n * D3 + d] = h;
    if (d < 3) H[n * D3 + D + d] = X[n * 3 + d];
}

// ---------------- 3. edge kernel (+ fused scatter) ----------------------------
// grid = 128 (1 tile of 64 edges each), 1024 threads, weights once per block.
#define ET    64
#define EPAD  137
#define SE_W   0                      // We1: 8576 (16B-aligned base)
#define SE_BE1 8576                   // 64
#define SE_WE2 (SE_BE1 + 64)          // 64
#define SE_B   (SE_WE2 + 64)          // 64*137 = 8768
#define SE_EW  (SE_B + ET * EPAD)     // 64
#define SE_SI  (SE_EW + 64)           // 64 ints
#define SE_SO  (SE_SI + 64)           // 64 ints
#define E_SMEM ((SE_SO + 64) * 4)     // 70656 B

template<bool SCATTER>
__global__ void __launch_bounds__(1024)
edge_kernel(const float* __restrict__ H,
            const float* __restrict__ We1, const float* __restrict__ be1,
            const float* __restrict__ We2, const float* __restrict__ be2,
            float* __restrict__ out) {
    extern __shared__ float sm[];
    int t = threadIdx.x;
    for (int i = t; i < F1 * D; i += 1024) sm[SE_W + i] = We1[i];
    if (t < D) { sm[SE_BE1 + t] = be1[t]; sm[SE_WE2 + t] = We2[t]; }
    int* sSi = (int*)(sm + SE_SI);
    int* sSo = (int*)(sm + SE_SO);
    int e0 = blockIdx.x * ET;
    if (t < ET) { sSi[t] = g_seg_i[e0 + t]; sSo[t] = g_seg_o[e0 + t]; }
    __syncthreads();

    // gather B = [bo | bi], edge-major
    for (int i = t; i < ET * F1; i += 1024) {
        int j = i / F1, k = i - j * F1;
        float v = (k < D3) ? H[sSo[j] * D3 + k] : H[sSi[j] * D3 + (k - D3)];
        sm[SE_B + j * EPAD + k] = v;
    }
    __syncthreads();

    if (t < 512) {
        int cg = t & 7;           // 8 output cols: 8cg .. 8cg+7
        int eg = t >> 3;          // edge 0..63
        const ulonglong2* W2p = (const ulonglong2*)(sm + SE_W);   // 16 ull2 per 64-col row
        const float* Bp = sm + SE_B + eg * EPAD;
        ull a0 = pack2(sm[SE_BE1 + 8 * cg + 0], sm[SE_BE1 + 8 * cg + 1]);
        ull a1 = pack2(sm[SE_BE1 + 8 * cg + 2], sm[SE_BE1 + 8 * cg + 3]);
        ull a2 = pack2(sm[SE_BE1 + 8 * cg + 4], sm[SE_BE1 + 8 * cg + 5]);
        ull a3 = pack2(sm[SE_BE1 + 8 * cg + 6], sm[SE_BE1 + 8 * cg + 7]);
        #pragma unroll 2
        for (int k = 0; k < F1; k++) {
            float b = Bp[k];
            ull bb = pack2(b, b);
            ulonglong2 wA = W2p[k * 16 + 2 * cg];
            ulonglong2 wB = W2p[k * 16 + 2 * cg + 1];
            a0 = fma2(bb, wA.x, a0); a1 = fma2(bb, wA.y, a1);
            a2 = fma2(bb, wB.x, a2); a3 = fma2(bb, wB.y, a3);
        }
        float h0, h1, h2, h3, h4, h5, h6, h7;
        unpack2(a0, h0, h1); unpack2(a1, h2, h3);
        unpack2(a2, h4, h5); unpack2(a3, h6, h7);
        float p = tanhf(h0) * sm[SE_WE2 + 8 * cg + 0] + tanhf(h1) * sm[SE_WE2 + 8 * cg + 1]
                + tanhf(h2) * sm[SE_WE2 + 8 * cg + 2] + tanhf(h3) * sm[SE_WE2 + 8 * cg + 3]
                + tanhf(h4) * sm[SE_WE2 + 8 * cg + 4] + tanhf(h5) * sm[SE_WE2 + 8 * cg + 5]
                + tanhf(h6) * sm[SE_WE2 + 8 * cg + 6] + tanhf(h7) * sm[SE_WE2 + 8 * cg + 7];
        #pragma unroll
        for (int off = 4; off; off >>= 1)
            p += __shfl_down_sync(0xffffffffu, p, off, 8);
        if (cg == 0) {
            float ew = sigmoidf_(p + be2[0]);
            sm[SE_EW + eg] = ew;
            if (!SCATTER) out[e0 + eg] = ew;
        }
    }
    __syncthreads();
    if (SCATTER) {
        for (int i = t; i < ET * D3; i += 1024) {
            int j = i / D3, k = i - j * D3;
            float ew = sm[SE_EW + j];
            atomicAdd(&g_MI[sSi[j] * D3 + k], ew * sm[SE_B + j * EPAD + k]);
            atomicAdd(&g_MO[sSo[j] * D3 + k], ew * sm[SE_B + j * EPAD + D3 + k]);
        }
    }
}

// ---------------- 4. node kernel (+ fused re-zero) ----------------------------
// grid = 128 (1 tile of 32 nodes), 1024 threads, weights once per block.
#define NT    32
#define MPAD  205
#define HPAD  72
#define SN_W1  0                        // 12864 (16B-aligned)
#define SN_W2  12864                    // 4096  (51456 B, 16B-aligned)
#define SN_BN1 (12864 + 4096)           // 64
#define SN_BN2 (SN_BN1 + 64)            // 64
#define SN_M   (SN_BN2 + 64)            // 32*205 = 6560
#define SN_H   (SN_M + NT * MPAD)       // 32*72  = 2304
#define N_SMEM ((SN_H + NT * HPAD) * 4) // 103808 B

__global__ void __launch_bounds__(1024)
node_kernel(const float* __restrict__ Hin, const float* __restrict__ X,
            const float* __restrict__ Wn1, const float* __restrict__ bn1,
            const float* __restrict__ Wn2, const float* __restrict__ bn2,
            float* __restrict__ Hout) {
    extern __shared__ float sm[];
    int t = threadIdx.x;
    for (int i = t; i < F2 * D; i += 1024) sm[SN_W1 + i] = Wn1[i];
    for (int i = t; i < D * D;  i += 1024) sm[SN_W2 + i] = Wn2[i];
    if (t < D) { sm[SN_BN1 + t] = bn1[t]; sm[SN_BN2 + t] = bn2[t]; }
    int n0 = blockIdx.x * NT;

    for (int i = t; i < NT * F2; i += 1024) {
        int j = i / F2, k = i - j * F2;
        int n = n0 + j;
        float v;
        if (k < D3)          v = g_MI[n * D3 + k];
        else if (k < 2 * D3) v = g_MO[n * D3 + (k - D3)];
        else                 v = Hin[n * D3 + (k - 2 * D3)];
        sm[SN_M + j * MPAD + k] = v;
    }
    __syncthreads();

    if (t < 256) {
        int cg = t & 7;
        int ng = t >> 3;
        const ulonglong2* W2p = (const ulonglong2*)(sm + SN_W1);
        const float* Mp = sm + SN_M + ng * MPAD;
        ull a0 = pack2(sm[SN_BN1 + 8 * cg + 0], sm[SN_BN1 + 8 * cg + 1]);
        ull a1 = pack2(sm[SN_BN1 + 8 * cg + 2], sm[SN_BN1 + 8 * cg + 3]);
        ull a2 = pack2(sm[SN_BN1 + 8 * cg + 4], sm[SN_BN1 + 8 * cg + 5]);
        ull a3 = pack2(sm[SN_BN1 + 8 * cg + 6], sm[SN_BN1 + 8 * cg + 7]);
        #pragma unroll 2
        for (int k = 0; k < F2; k++) {
            float b = Mp[k];
            ull bb = pack2(b, b);
            ulonglong2 wA = W2p[k * 16 + 2 * cg];
            ulonglong2 wB = W2p[k * 16 + 2 * cg + 1];
            a0 = fma2(bb, wA.x, a0); a1 = fma2(bb, wA.y, a1);
            a2 = fma2(bb, wB.x, a2); a3 = fma2(bb, wB.y, a3);
        }
        float h0, h1, h2, h3, h4, h5, h6, h7;
        unpack2(a0, h0, h1); unpack2(a1, h2, h3);
        unpack2(a2, h4, h5); unpack2(a3, h6, h7);
        float* hp = sm + SN_H + ng * HPAD + 8 * cg;
        hp[0] = tanhf(h0); hp[1] = tanhf(h1); hp[2] = tanhf(h2); hp[3] = tanhf(h3);
        hp[4] = tanhf(h4); hp[5] = tanhf(h5); hp[6] = tanhf(h6); hp[7] = tanhf(h7);
    }
    __syncthreads();
    if (t < 256) {
        int cg = t & 7;
        int ng = t >> 3;
        const ulonglong2* W2p = (const ulonglong2*)(sm + SN_W2);
        const float* hp = sm + SN_H + ng * HPAD;
        ull a0 = pack2(sm[SN_BN2 + 8 * cg + 0], sm[SN_BN2 + 8 * cg + 1]);
        ull a1 = pack2(sm[SN_BN2 + 8 * cg + 2], sm[SN_BN2 + 8 * cg + 3]);
        ull a2 = pack2(sm[SN_BN2 + 8 * cg + 4], sm[SN_BN2 + 8 * cg + 5]);
        ull a3 = pack2(sm[SN_BN2 + 8 * cg + 6], sm[SN_BN2 + 8 * cg + 7]);
        #pragma unroll 4
        for (int k = 0; k < D; k++) {
            float b = hp[k];
            ull bb = pack2(b, b);
            ulonglong2 wA = W2p[k * 16 + 2 * cg];
            ulonglong2 wB = W2p[k * 16 + 2 * cg + 1];
            a0 = fma2(bb, wA.x, a0); a1 = fma2(bb, wA.y, a1);
            a2 = fma2(bb, wB.x, a2); a3 = fma2(bb, wB.y, a3);
        }
        float o0, o1, o2, o3, o4, o5, o6, o7;
        unpack2(a0, o0, o1); unpack2(a1, o2, o3);
        unpack2(a2, o4, o5); unpack2(a3, o6, o7);
        float* op = Hout + (n0 + ng) * D3 + 8 * cg;
        op[0] = sigmoidf_(o0); op[1] = sigmoidf_(o1);
        op[2] = sigmoidf_(o2); op[3] = sigmoidf_(o3);
        op[4] = sigmoidf_(o4); op[5] = sigmoidf_(o5);
        op[6] = sigmoidf_(o6); op[7] = sigmoidf_(o7);
    }
    if (t < NT * 3) {
        int j = t / 3, c = t - j * 3;
        Hout[(n0 + j) * D3 + D + c] = X[(n0 + j) * 3 + c];
    }
    // re-zero this tile's MI/MO for the next accumulation
    for (int i = t; i < NT * D3; i += 1024) {
        int j = i / D3, k = i - j * D3;
        g_MI[(n0 + j) * D3 + k] = 0.f;
        g_MO[(n0 + j) * D3 + k] = 0.f;
    }
}

// ---------------- launcher ----------------------------------------------------
extern "C" void kernel_launch(void* const* d_in, const int* in_sizes, int n_in,
                              void* d_out, int out_size) {
    const float* X    = (const float*)d_in[0];
    const float* Ri   = (const float*)d_in[1];
    const float* Ro   = (const float*)d_in[2];
    const float* W_in = (const float*)d_in[3];
    const float* b_in = (const float*)d_in[4];
    const float* We1  = (const float*)d_in[5];
    const float* be1  = (const float*)d_in[6];
    const float* We2  = (const float*)d_in[7];
    const float* be2  = (const float*)d_in[8];
    const float* Wn1  = (const float*)d_in[9];
    const float* bn1  = (const float*)d_in[10];
    const float* Wn2  = (const float*)d_in[11];
    const float* bn2  = (const float*)d_in[12];
    float* out = (float*)d_out;

    float *pH0, *pH1;
    cudaGetSymbolAddress((void**)&pH0, g_H0);
    cudaGetSymbolAddress((void**)&pH1, g_H1);

    static int attr_done = 0;
    if (!attr_done) {
        cudaFuncSetAttribute(edge_kernel<true>,
                             cudaFuncAttributeMaxDynamicSharedMemorySize, E_SMEM);
        cudaFuncSetAttribute(edge_kernel<false>,
                             cudaFuncAttributeMaxDynamicSharedMemorySize, E_SMEM);
        cudaFuncSetAttribute(node_kernel,
                             cudaFuncAttributeMaxDynamicSharedMemorySize, N_SMEM);
        attr_done = 1;
    }

    // 1. extract (268 MB, pure stream, max MLP)
    extract_kernel<<<16384, 256>>>(Ri, Ro);
    // 2. input net
    input_kernel<<<(N_NODES * D) / 256, 256>>>(X, W_in, b_in, pH0);

    float* Hc = pH0;
    float* Hn = pH1;
    for (int it = 0; it < 3; it++) {
        edge_kernel<true><<<N_EDGES / ET, 1024, E_SMEM>>>(Hc, We1, be1, We2, be2, nullptr);
        node_kernel<<<N_NODES / NT, 1024, N_SMEM>>>(Hc, X, Wn1, bn1, Wn2, bn2, Hn);
        float* tmp = Hc; Hc = Hn; Hn = tmp;
    }
    edge_kernel<false><<<N_EDGES / ET, 1024, E_SMEM>>>(Hc, We1, be1, We2, be2, out);
}